// round 7
// baseline (speedup 1.0000x reference)
#include <cuda_runtime.h>
#include <cuda_bf16.h>
#include <cstdint>

#define NN 100000
#define EE 1600000
#define TILE_M 128
#define NTILES ((NN + TILE_M - 1) / TILE_M)   // 782

typedef uint32_t u32;

// ---------------- scratch (static device globals; no allocations) ----------
__device__ __nv_bfloat16  g_hhi[(NN + 128) * 64];  // node features, bf16 hi part
__device__ __nv_bfloat16  g_hlo[(NN + 128) * 64];  // node features, bf16 lo part
__device__ float          g_pq[NN * 128];  // p (cols 0-63), q (cols 64-127)
__device__ int            g_src[EE];       // int32 source indices
__device__ unsigned       g_gmax[64];      // global max bits (values >= 0)
__device__ float          g_c128[128];     // head constant: g @ Wa[64:128] + ba
__device__ __nv_bfloat16  g_whi[5 * 128 * 64];  // weight hi parts, [n][k] flat
__device__ __nv_bfloat16  g_wlo[5 * 128 * 64];  // weight lo parts

// ---------------- convert (fused gmax zero + dtype detect) ------------------
__global__ void convert_kernel(const int* __restrict__ ei) {
    __shared__ int s64;
    if (blockIdx.x == 0 && threadIdx.x < 64) g_gmax[threadIdx.x] = 0u;
    if (threadIdx.x == 0) {
        // int64 layout => odd words of src row all zero (0<=src<1e5);
        // int32 layout => P(all 64 zero) ~ 1e-320.
        int z = 0;
        for (int i = 0; i < 64; i++) z += (ei[2 * i + 1] == 0) ? 1 : 0;
        s64 = (z == 64) ? 1 : 0;
    }
    __syncthreads();
    int e = blockIdx.x * blockDim.x + threadIdx.x;
    if (e < EE) g_src[e] = s64 ? ei[2 * e] : ei[e];
}

// ---------------- layer 1: warp-per-node + fused weight prep ---------------
// blocks 0..12499: 8 nodes each (warp per node). blocks 12500..12504: wprep.
// wprep: layers 0-3: Wc[n][k] = (n<64) ? W[k][n]-W[k+64][n] : W[k+64][n-64]
//        layer 4:    Wc[n][k] = Wa[k][n]
__global__ void layer1_kernel(const float* __restrict__ x,
                              const float* __restrict__ W1,
                              const float* __restrict__ b1,
                              const float* __restrict__ Wl0,
                              const float* __restrict__ Wl1,
                              const float* __restrict__ Wl2,
                              const float* __restrict__ Wl3,
                              const float* __restrict__ Wa) {
    if (blockIdx.x >= 12500) {
        int b = blockIdx.x - 12500;
        const float* W = (b == 0) ? Wl0 : (b == 1) ? Wl1 : (b == 2) ? Wl2
                       : (b == 3) ? Wl3 : Wa;
        for (int i = threadIdx.x; i < 8192; i += 256) {
            int n = i >> 6, k = i & 63;
            float wv;
            if (b < 4)
                wv = (n < 64) ? (W[k * 64 + n] - W[(k + 64) * 64 + n])
                              : W[(k + 64) * 64 + (n - 64)];
            else
                wv = W[k * 128 + n];
            __nv_bfloat16 hi = __float2bfloat16(wv);
            __nv_bfloat16 lo = __float2bfloat16(wv - __bfloat162float(hi));
            g_whi[b * 8192 + i] = hi;
            g_wlo[b * 8192 + i] = lo;
        }
        return;
    }
    __shared__ float sW[384];   // W1: 6 rows x 64
    __shared__ float sb[64];
    int tid = threadIdx.x;
    for (int i = tid; i < 448; i += 256) {
        if (i < 384) sW[i] = W1[i];
        else         sb[i - 384] = b1[i - 384];
    }
    __syncthreads();
    int lane = tid & 31;
    int node = blockIdx.x * 8 + (tid >> 5);
    float xv = (lane < 3) ? x[node * 3 + lane] : 0.f;
    float x0 = __shfl_sync(0xffffffffu, xv, 0);
    float x1 = __shfl_sync(0xffffffffu, xv, 1);
    float x2 = __shfl_sync(0xffffffffu, xv, 2);
    int c = lane * 2;
    float w30 = sW[192 + c], w31 = sW[193 + c];
    float w40 = sW[256 + c], w41 = sW[257 + c];
    float w50 = sW[320 + c], w51 = sW[321 + c];
    float q0 = x0 * w30 + x1 * w40 + x2 * w50;
    float q1 = x0 * w31 + x1 * w41 + x2 * w51;
    float p0 = sb[c]     + x0 * (sW[c] - w30)     + x1 * (sW[64 + c] - w40)
                         + x2 * (sW[128 + c] - w50);
    float p1 = sb[c + 1] + x0 * (sW[c + 1] - w31) + x1 * (sW[65 + c] - w41)
                         + x2 * (sW[129 + c] - w51);
    *(float2*)(g_pq + node * 128 + c)      = make_float2(p0, p1);
    *(float2*)(g_pq + node * 128 + 64 + c) = make_float2(q0, q1);
}

// ---------------- edge max -> bf16 hi/lo output (+ fused global max) --------
__global__ void edge_kernel(int dogmax) {
    __shared__ unsigned sm[64];
    int w    = (blockIdx.x * blockDim.x + threadIdx.x) >> 5;  // grid exact
    int lane = threadIdx.x & 31;
    int s = (lane < 16) ? g_src[w * 16 + lane] : 0;
    float2 m = make_float2(-3.402823466e38f, -3.402823466e38f);
    const float* pq = g_pq;
#pragma unroll
    for (int k = 0; k < 16; k++) {
        int j = __shfl_sync(0xffffffffu, s, k);
        float2 v = *(const float2*)(pq + j * 128 + 64 + lane * 2);
        m.x = fmaxf(m.x, v.x);
        m.y = fmaxf(m.y, v.y);
    }
    float2 p = *(const float2*)(pq + w * 128 + lane * 2);
    float rx = fmaxf(p.x + m.x, 0.f);
    float ry = fmaxf(p.y + m.y, 0.f);
    __nv_bfloat16 h0 = __float2bfloat16(rx);
    __nv_bfloat16 h1 = __float2bfloat16(ry);
    __nv_bfloat16 l0 = __float2bfloat16(rx - __bfloat162float(h0));
    __nv_bfloat16 l1 = __float2bfloat16(ry - __bfloat162float(h1));
    *(__nv_bfloat162*)(g_hhi + w * 64 + lane * 2) = __halves2bfloat162(h0, h1);
    *(__nv_bfloat162*)(g_hlo + w * 64 + lane * 2) = __halves2bfloat162(l0, l1);
    if (dogmax) {
        if (threadIdx.x < 64) sm[threadIdx.x] = 0u;
        __syncthreads();
        atomicMax(&sm[lane * 2],     __float_as_uint(rx));   // r >= 0
        atomicMax(&sm[lane * 2 + 1], __float_as_uint(ry));
        __syncthreads();
        if (threadIdx.x < 64) atomicMax(&g_gmax[threadIdx.x], sm[threadIdx.x]);
    }
}

// ---------------- mma / ldmatrix / cp.async helpers -------------------------
static __device__ __forceinline__ void mma16816(float d[4], const u32 a[4],
                                                const u32 b[2]) {
    asm volatile(
        "mma.sync.aligned.m16n8k16.row.col.f32.bf16.bf16.f32 "
        "{%0,%1,%2,%3}, {%4,%5,%6,%7}, {%8,%9}, {%0,%1,%2,%3};"
        : "+f"(d[0]), "+f"(d[1]), "+f"(d[2]), "+f"(d[3])
        : "r"(a[0]), "r"(a[1]), "r"(a[2]), "r"(a[3]), "r"(b[0]), "r"(b[1]));
}
static __device__ __forceinline__ void ldsm4(u32 r[4], u32 addr) {
    asm volatile("ldmatrix.sync.aligned.m8n8.x4.shared.b16 {%0,%1,%2,%3}, [%4];"
        : "=r"(r[0]), "=r"(r[1]), "=r"(r[2]), "=r"(r[3]) : "r"(addr));
}
static __device__ __forceinline__ u32 smem_u32(const void* p) {
    u32 a;
    asm("{ .reg .u64 t; cvta.to.shared.u64 t, %1; cvt.u32.u64 %0, t; }"
        : "=r"(a) : "l"(p));
    return a;
}
static __device__ __forceinline__ void cpasync16(u32 dst, const void* src) {
    asm volatile("cp.async.cg.shared.global [%0], [%1], 16;"
        :: "r"(dst), "l"(src) : "memory");
}
static __device__ __forceinline__ void cpasync_commit() {
    asm volatile("cp.async.commit_group;" ::: "memory");
}
static __device__ __forceinline__ void cpasync_wait1() {
    asm volatile("cp.async.wait_group 1;" ::: "memory");
}
static __device__ __forceinline__ void cpasync_wait0() {
    asm volatile("cp.async.wait_group 0;" ::: "memory");
}

// ---------------- tensor-core GEMM: h[N,64] @ Wc[64,128] -> g_pq ------------
// Grid = NTILES. CTA tile 128M x 128N, 8 warps, warp tile 32M x 64N via
// m16n8k16 bf16 mma. 3-pass hi/lo split: Ahi*Bhi + Alo*Bhi + Ahi*Blo.
// 2-stage cp.async pipeline: group0 = Ahi+Bhi -> hi*hi pass overlaps group1
// (Alo+Blo) in flight. Smem rows padded to 72 bf16: ldmatrix conflict-free.
// mode 0: bias on cols 0-63.  mode 1: bias g_c128, relu at store.
__global__ void __launch_bounds__(256) tc_gemm_kernel(int layer,
                                                      const float* __restrict__ bias,
                                                      int mode) {
    extern __shared__ unsigned char smem[];
    // sAhi [128][72] @0, sAlo @18432, sBhi [128][72] @36864, sBlo @55296,
    // bias f32[128] @73728. total 74240 B
    float* sB = (float*)(smem + 73728);
    int tid = threadIdx.x;
    int nb  = blockIdx.x * TILE_M;

    u32 sbase = smem_u32(smem);

    // group 0: A-hi + B-hi (1024 16B chunks each; chunk c -> row c>>3, ch c&7)
    {
        const char* ah = (const char*)(g_hhi + (size_t)nb * 64);
        const char* wh = (const char*)(g_whi + layer * 8192);
#pragma unroll
        for (int c = tid; c < 1024; c += 256) {
            u32 off = (u32)(c >> 3) * 144 + (u32)(c & 7) * 16;
            cpasync16(sbase + off, ah + c * 16);
            cpasync16(sbase + 36864 + off, wh + c * 16);
        }
    }
    cpasync_commit();
    // group 1: A-lo + B-lo
    {
        const char* al = (const char*)(g_hlo + (size_t)nb * 64);
        const char* wl = (const char*)(g_wlo + layer * 8192);
#pragma unroll
        for (int c = tid; c < 1024; c += 256) {
            u32 off = (u32)(c >> 3) * 144 + (u32)(c & 7) * 16;
            cpasync16(sbase + 18432 + off, al + c * 16);
            cpasync16(sbase + 55296 + off, wl + c * 16);
        }
    }
    cpasync_commit();
    if (tid < 128)
        sB[tid] = (mode == 0) ? ((tid < 64) ? bias[tid] : 0.f) : g_c128[tid];

    int lane = tid & 31;
    int wid  = tid >> 5;
    int wm   = wid & 3;      // rows wm*32..+32
    int wn   = wid >> 2;     // cols wn*64..+64

    u32 aHi = sbase + ((wm * 32 + (lane & 15)) * 72 + (lane >> 4) * 8) * 2;
    u32 aLo = aHi + 18432;
    int brow = wn * 64 + (lane & 7) + (lane >> 4) * 8;
    u32 bHi = sbase + 36864 + (brow * 72 + ((lane >> 3) & 1) * 8) * 2;
    u32 bLo = bHi + 18432;

    float d[2][8][4];
#pragma unroll
    for (int mt = 0; mt < 2; mt++)
#pragma unroll
        for (int nf = 0; nf < 8; nf++)
#pragma unroll
            for (int j = 0; j < 4; j++) d[mt][nf][j] = 0.f;

    cpasync_wait1();     // group 0 (hi parts) resident
    __syncthreads();

    // phase 1: Ahi * Bhi
#pragma unroll
    for (int kk = 0; kk < 4; kk++) {
        int ko = kk * 32;
        u32 ah[2][4], bh[4][4];
        ldsm4(ah[0], aHi + ko);
        ldsm4(ah[1], aHi + 2304 + ko);
#pragma unroll
        for (int p = 0; p < 4; p++) ldsm4(bh[p], bHi + p * 2304 + ko);
#pragma unroll
        for (int mt = 0; mt < 2; mt++)
#pragma unroll
            for (int nf = 0; nf < 8; nf++)
                mma16816(d[mt][nf], ah[mt], &bh[nf >> 1][(nf & 1) * 2]);
    }

    cpasync_wait0();     // group 1 (lo parts) resident
    __syncthreads();

    // phase 2: Alo * Bhi  +  Ahi * Blo
#pragma unroll
    for (int kk = 0; kk < 4; kk++) {
        int ko = kk * 32;
        u32 aa[2][4], bb[4][4];
        ldsm4(aa[0], aLo + ko);
        ldsm4(aa[1], aLo + 2304 + ko);
#pragma unroll
        for (int p = 0; p < 4; p++) ldsm4(bb[p], bHi + p * 2304 + ko);
#pragma unroll
        for (int mt = 0; mt < 2; mt++)
#pragma unroll
            for (int nf = 0; nf < 8; nf++)
                mma16816(d[mt][nf], aa[mt], &bb[nf >> 1][(nf & 1) * 2]);
        ldsm4(aa[0], aHi + ko);
        ldsm4(aa[1], aHi + 2304 + ko);
#pragma unroll
        for (int p = 0; p < 4; p++) ldsm4(bb[p], bLo + p * 2304 + ko);
#pragma unroll
        for (int mt = 0; mt < 2; mt++)
#pragma unroll
            for (int nf = 0; nf < 8; nf++)
                mma16816(d[mt][nf], aa[mt], &bb[nf >> 1][(nf & 1) * 2]);
    }

    // Epilogue
    int r = lane >> 2, q = lane & 3;
#pragma unroll
    for (int mt = 0; mt < 2; mt++) {
        int row0 = nb + wm * 32 + mt * 16 + r;
#pragma unroll
        for (int nf = 0; nf < 8; nf++) {
            int gcol = wn * 64 + nf * 8 + 2 * q;
            float bx = sB[gcol], by = sB[gcol + 1];
            float2 v0 = make_float2(d[mt][nf][0] + bx, d[mt][nf][1] + by);
            float2 v1 = make_float2(d[mt][nf][2] + bx, d[mt][nf][3] + by);
            if (mode == 1) {
                v0.x = fmaxf(v0.x, 0.f); v0.y = fmaxf(v0.y, 0.f);
                v1.x = fmaxf(v1.x, 0.f); v1.y = fmaxf(v1.y, 0.f);
            }
            if (row0 < NN)     *(float2*)(g_pq + row0 * 128 + gcol)       = v0;
            if (row0 + 8 < NN) *(float2*)(g_pq + (row0 + 8) * 128 + gcol) = v1;
        }
    }
}

// ---------------- c128 = ba + g @ Wa[64:128] --------------------------------
__global__ void c128_kernel(const float* __restrict__ Wa,
                            const float* __restrict__ ba) {
    int t = threadIdx.x;  // 128 threads
    float s = ba[t];
#pragma unroll 8
    for (int c = 0; c < 64; c++)
        s += __uint_as_float(g_gmax[c]) * Wa[(64 + c) * 128 + t];
    g_c128[t] = s;
}

// ---------------- head stage 2: out = x + r @ Wb + bb ----------------------
__global__ void head2_kernel(const float* __restrict__ Wb,
                             const float* __restrict__ bb,
                             const float* __restrict__ x,
                             float* __restrict__ out) {
    __shared__ float sWb[384];
    for (int i = threadIdx.x; i < 384; i += 256) sWb[i] = Wb[i];
    __syncthreads();
    int w    = (blockIdx.x * blockDim.x + threadIdx.x) >> 5;
    int lane = threadIdx.x & 31;
    if (w >= NN) return;
    float4 r4 = ((const float4*)(g_pq + w * 128))[lane];
    int t = lane * 4;
    float a0 = r4.x * sWb[t * 3 + 0] + r4.y * sWb[t * 3 + 3] +
               r4.z * sWb[t * 3 + 6] + r4.w * sWb[t * 3 + 9];
    float a1 = r4.x * sWb[t * 3 + 1] + r4.y * sWb[t * 3 + 4] +
               r4.z * sWb[t * 3 + 7] + r4.w * sWb[t * 3 + 10];
    float a2 = r4.x * sWb[t * 3 + 2] + r4.y * sWb[t * 3 + 5] +
               r4.z * sWb[t * 3 + 8] + r4.w * sWb[t * 3 + 11];
#pragma unroll
    for (int off = 16; off > 0; off >>= 1) {
        a0 += __shfl_down_sync(0xffffffffu, a0, off);
        a1 += __shfl_down_sync(0xffffffffu, a1, off);
        a2 += __shfl_down_sync(0xffffffffu, a2, off);
    }
    if (lane == 0) {
        out[w * 3 + 0] = x[w * 3 + 0] + bb[0] + a0;
        out[w * 3 + 1] = x[w * 3 + 1] + bb[1] + a1;
        out[w * 3 + 2] = x[w * 3 + 2] + bb[2] + a2;
    }
}

// ---------------- launch ----------------------------------------------------
extern "C" void kernel_launch(void* const* d_in, const int* in_sizes, int n_in,
                              void* d_out, int out_size) {
    (void)in_sizes; (void)n_in; (void)out_size;
    const float* x  = (const float*)d_in[0];
    const int*   ei = (const int*)d_in[1];
    const float* W1 = (const float*)d_in[2];
    const float* b1 = (const float*)d_in[3];
    const float* Wl[4] = {(const float*)d_in[4], (const float*)d_in[6],
                          (const float*)d_in[8], (const float*)d_in[10]};
    const float* bl[4] = {(const float*)d_in[5], (const float*)d_in[7],
                          (const float*)d_in[9], (const float*)d_in[11]};
    const float* Wa = (const float*)d_in[12];
    const float* ba = (const float*)d_in[13];
    const float* Wb = (const float*)d_in[14];
    const float* bb = (const float*)d_in[15];
    float* out = (float*)d_out;

    const int GEMM_SMEM = 74240;
    static bool attr_set = false;
    if (!attr_set) {
        cudaFuncSetAttribute(tc_gemm_kernel,
                             cudaFuncAttributeMaxDynamicSharedMemorySize,
                             GEMM_SMEM);
        attr_set = true;
    }

    convert_kernel<<<(EE + 255) / 256, 256>>>(ei);                        // #1
    layer1_kernel<<<12505, 256>>>(x, W1, b1, Wl[0], Wl[1], Wl[2], Wl[3], Wa); // #2
    edge_kernel<<<(NN * 32) / 256, 256>>>(0);                             // #3

    for (int l = 0; l < 4; l++) {
        tc_gemm_kernel<<<NTILES, 256, GEMM_SMEM>>>(l, bl[l], 0);          // #4 (l=0)
        edge_kernel<<<(NN * 32) / 256, 256>>>(l == 3 ? 1 : 0);
    }

    c128_kernel<<<1, 128>>>(Wa, ba);
    tc_gemm_kernel<<<NTILES, 256, GEMM_SMEM>>>(4, ba, 1);
    head2_kernel<<<(NN * 32) / 256, 256>>>(Wb, bb, x, out);
}

// round 9
// speedup vs baseline: 1.0172x; 1.0172x over previous
#include <cuda_runtime.h>
#include <cuda_bf16.h>
#include <cstdint>

#define NN 100000
#define EE 1600000
#define TILE_M 128
#define NTILES ((NN + TILE_M - 1) / TILE_M)   // 782
#define PGRID 296                             // persistent GEMM grid (2/SM)

typedef uint32_t u32;

// ---------------- scratch (static device globals; no allocations) ----------
__device__ __nv_bfloat16  g_hhi[(NN + 128) * 64];  // node features, bf16 hi part
__device__ __nv_bfloat16  g_hlo[(NN + 128) * 64];  // node features, bf16 lo part
__device__ float          g_pq[NN * 128];  // p (cols 0-63), q (cols 64-127)
__device__ int            g_src[EE];       // int32 source indices
__device__ unsigned       g_gmax[64];      // global max bits (values >= 0)
__device__ float          g_c128[128];     // head constant: g @ Wa[64:128] + ba
__device__ __nv_bfloat16  g_whi[5 * 128 * 64];  // weight hi parts, [n][k] flat
__device__ __nv_bfloat16  g_wlo[5 * 128 * 64];  // weight lo parts

// ---------------- convert (fused gmax zero + dtype detect) ------------------
__global__ void convert_kernel(const int* __restrict__ ei) {
    __shared__ int s64;
    if (blockIdx.x == 0 && threadIdx.x < 64) g_gmax[threadIdx.x] = 0u;
    if (threadIdx.x == 0) {
        // int64 layout => odd words of src row all zero (0<=src<1e5);
        // int32 layout => P(all 64 zero) ~ 1e-320.
        int z = 0;
        for (int i = 0; i < 64; i++) z += (ei[2 * i + 1] == 0) ? 1 : 0;
        s64 = (z == 64) ? 1 : 0;
    }
    __syncthreads();
    int e = blockIdx.x * blockDim.x + threadIdx.x;
    if (e < EE) g_src[e] = s64 ? ei[2 * e] : ei[e];
}

// ---------------- layer 1: warp-per-node + fused weight prep ---------------
__global__ void layer1_kernel(const float* __restrict__ x,
                              const float* __restrict__ W1,
                              const float* __restrict__ b1,
                              const float* __restrict__ Wl0,
                              const float* __restrict__ Wl1,
                              const float* __restrict__ Wl2,
                              const float* __restrict__ Wl3,
                              const float* __restrict__ Wa) {
    if (blockIdx.x >= 12500) {
        int b = blockIdx.x - 12500;
        const float* W = (b == 0) ? Wl0 : (b == 1) ? Wl1 : (b == 2) ? Wl2
                       : (b == 3) ? Wl3 : Wa;
        for (int i = threadIdx.x; i < 8192; i += 256) {
            int n = i >> 6, k = i & 63;
            float wv;
            if (b < 4)
                wv = (n < 64) ? (W[k * 64 + n] - W[(k + 64) * 64 + n])
                              : W[(k + 64) * 64 + (n - 64)];
            else
                wv = W[k * 128 + n];
            __nv_bfloat16 hi = __float2bfloat16(wv);
            __nv_bfloat16 lo = __float2bfloat16(wv - __bfloat162float(hi));
            g_whi[b * 8192 + i] = hi;
            g_wlo[b * 8192 + i] = lo;
        }
        return;
    }
    __shared__ float sW[384];   // W1: 6 rows x 64
    __shared__ float sb[64];
    int tid = threadIdx.x;
    for (int i = tid; i < 448; i += 256) {
        if (i < 384) sW[i] = W1[i];
        else         sb[i - 384] = b1[i - 384];
    }
    __syncthreads();
    int lane = tid & 31;
    int node = blockIdx.x * 8 + (tid >> 5);
    float xv = (lane < 3) ? x[node * 3 + lane] : 0.f;
    float x0 = __shfl_sync(0xffffffffu, xv, 0);
    float x1 = __shfl_sync(0xffffffffu, xv, 1);
    float x2 = __shfl_sync(0xffffffffu, xv, 2);
    int c = lane * 2;
    float w30 = sW[192 + c], w31 = sW[193 + c];
    float w40 = sW[256 + c], w41 = sW[257 + c];
    float w50 = sW[320 + c], w51 = sW[321 + c];
    float q0 = x0 * w30 + x1 * w40 + x2 * w50;
    float q1 = x0 * w31 + x1 * w41 + x2 * w51;
    float p0 = sb[c]     + x0 * (sW[c] - w30)     + x1 * (sW[64 + c] - w40)
                         + x2 * (sW[128 + c] - w50);
    float p1 = sb[c + 1] + x0 * (sW[c + 1] - w31) + x1 * (sW[65 + c] - w41)
                         + x2 * (sW[129 + c] - w51);
    *(float2*)(g_pq + node * 128 + c)      = make_float2(p0, p1);
    *(float2*)(g_pq + node * 128 + 64 + c) = make_float2(q0, q1);
}

// ---------------- edge max: 2 nodes per warp, float4 lanes ------------------
__global__ void edge_kernel(int dogmax) {
    __shared__ unsigned sm[64];
    int gw   = (blockIdx.x * blockDim.x + threadIdx.x) >> 5;  // warp: 2 nodes
    int lane = threadIdx.x & 31;
    int half = lane >> 4;
    int hl   = lane & 15;
    int node = gw * 2 + half;
    int s = g_src[gw * 32 + lane];   // lanes 0-15: node0 srcs, 16-31: node1
    float4 m = make_float4(-3.402823466e38f, -3.402823466e38f,
                           -3.402823466e38f, -3.402823466e38f);
    const float* pq = g_pq;
#pragma unroll
    for (int k = 0; k < 16; k++) {
        int j = __shfl_sync(0xffffffffu, s, (half << 4) + k);
        float4 v = *(const float4*)(pq + j * 128 + 64 + hl * 4);
        m.x = fmaxf(m.x, v.x);
        m.y = fmaxf(m.y, v.y);
        m.z = fmaxf(m.z, v.z);
        m.w = fmaxf(m.w, v.w);
    }
    float4 p = *(const float4*)(pq + node * 128 + hl * 4);
    float r0 = fmaxf(p.x + m.x, 0.f);
    float r1 = fmaxf(p.y + m.y, 0.f);
    float r2 = fmaxf(p.z + m.z, 0.f);
    float r3 = fmaxf(p.w + m.w, 0.f);
    __nv_bfloat16 h0 = __float2bfloat16(r0), h1 = __float2bfloat16(r1);
    __nv_bfloat16 h2 = __float2bfloat16(r2), h3 = __float2bfloat16(r3);
    __nv_bfloat16 l0 = __float2bfloat16(r0 - __bfloat162float(h0));
    __nv_bfloat16 l1 = __float2bfloat16(r1 - __bfloat162float(h1));
    __nv_bfloat16 l2 = __float2bfloat16(r2 - __bfloat162float(h2));
    __nv_bfloat16 l3 = __float2bfloat16(r3 - __bfloat162float(h3));
    __nv_bfloat162 hp0 = __halves2bfloat162(h0, h1);
    __nv_bfloat162 hp1 = __halves2bfloat162(h2, h3);
    __nv_bfloat162 lp0 = __halves2bfloat162(l0, l1);
    __nv_bfloat162 lp1 = __halves2bfloat162(l2, l3);
    uint2 hv = make_uint2(*(u32*)&hp0, *(u32*)&hp1);
    uint2 lv = make_uint2(*(u32*)&lp0, *(u32*)&lp1);
    *(uint2*)(g_hhi + node * 64 + hl * 4) = hv;
    *(uint2*)(g_hlo + node * 64 + hl * 4) = lv;
    if (dogmax) {
        if (threadIdx.x < 64) sm[threadIdx.x] = 0u;
        __syncthreads();
        atomicMax(&sm[hl * 4 + 0], __float_as_uint(r0));   // r >= 0
        atomicMax(&sm[hl * 4 + 1], __float_as_uint(r1));
        atomicMax(&sm[hl * 4 + 2], __float_as_uint(r2));
        atomicMax(&sm[hl * 4 + 3], __float_as_uint(r3));
        __syncthreads();
        if (threadIdx.x < 64) atomicMax(&g_gmax[threadIdx.x], sm[threadIdx.x]);
    }
}

// ---------------- mma / ldmatrix / cp.async helpers -------------------------
static __device__ __forceinline__ void mma16816(float d[4], const u32 a[4],
                                                const u32 b[2]) {
    asm volatile(
        "mma.sync.aligned.m16n8k16.row.col.f32.bf16.bf16.f32 "
        "{%0,%1,%2,%3}, {%4,%5,%6,%7}, {%8,%9}, {%0,%1,%2,%3};"
        : "+f"(d[0]), "+f"(d[1]), "+f"(d[2]), "+f"(d[3])
        : "r"(a[0]), "r"(a[1]), "r"(a[2]), "r"(a[3]), "r"(b[0]), "r"(b[1]));
}
static __device__ __forceinline__ void ldsm4(u32 r[4], u32 addr) {
    asm volatile("ldmatrix.sync.aligned.m8n8.x4.shared.b16 {%0,%1,%2,%3}, [%4];"
        : "=r"(r[0]), "=r"(r[1]), "=r"(r[2]), "=r"(r[3]) : "r"(addr));
}
static __device__ __forceinline__ u32 smem_u32(const void* p) {
    u32 a;
    asm("{ .reg .u64 t; cvta.to.shared.u64 t, %1; cvt.u32.u64 %0, t; }"
        : "=r"(a) : "l"(p));
    return a;
}
static __device__ __forceinline__ void cpasync16(u32 dst, const void* src) {
    asm volatile("cp.async.cg.shared.global [%0], [%1], 16;"
        :: "r"(dst), "l"(src) : "memory");
}
static __device__ __forceinline__ void cpasync_commit() {
    asm volatile("cp.async.commit_group;" ::: "memory");
}
static __device__ __forceinline__ void cpasync_wait1() {
    asm volatile("cp.async.wait_group 1;" ::: "memory");
}
static __device__ __forceinline__ void cpasync_wait0() {
    asm volatile("cp.async.wait_group 0;" ::: "memory");
}

// ---------------- persistent tensor-core GEMM: h @ Wc[64,128] -> g_pq -------
// Grid = PGRID (2 CTAs/SM). Each CTA: load B (hi+lo) ONCE, then loop tiles
// blockIdx.x, +PGRID, ... with a 2-stage double-buffered cp.async A pipeline
// (prefetch tile i+2 before epilogue of tile i). 8 warps, warp tile 32Mx64N,
// 3-pass bf16 hi/lo split (Ahi*Bhi + Alo*Bhi + Ahi*Blo), fp32 accum.
// Smem rows padded to 72 bf16 (144B): ldmatrix conflict-free.
// Layout: Bhi @0, Blo @18432, A s0 hi/lo @36864/@55296,
//         A s1 hi/lo @73728/@92160, bias @110592. Total 111104 B.
// mode 0: bias on cols 0-63.  mode 1: bias g_c128, relu at store.
__global__ void __launch_bounds__(256, 2) tc_gemm_kernel(int layer,
                                                         const float* __restrict__ bias,
                                                         int mode) {
    extern __shared__ unsigned char smem[];
    float* sB = (float*)(smem + 110592);
    int tid = threadIdx.x;
    u32 sbase = smem_u32(smem);

    // B once (group 0)
    {
        const char* wh = (const char*)(g_whi + layer * 8192);
        const char* wl = (const char*)(g_wlo + layer * 8192);
#pragma unroll
        for (int c = tid; c < 1024; c += 256) {
            u32 off = (u32)(c >> 3) * 144 + (u32)(c & 7) * 16;
            cpasync16(sbase + off, wh + c * 16);
            cpasync16(sbase + 18432 + off, wl + c * 16);
        }
    }
    cpasync_commit();

    int ntiles = (NTILES - blockIdx.x + PGRID - 1) / PGRID;

    // A prefetch for first two tiles (groups 1, 2)
#pragma unroll 1
    for (int pf = 0; pf < 2; pf++) {
        if (pf < ntiles) {
            int tile = blockIdx.x + pf * PGRID;
            const char* ah = (const char*)(g_hhi + (size_t)tile * TILE_M * 64);
            const char* al = (const char*)(g_hlo + (size_t)tile * TILE_M * 64);
            u32 sb_ = sbase + 36864 + (u32)pf * 36864;
#pragma unroll
            for (int c = tid; c < 1024; c += 256) {
                u32 off = (u32)(c >> 3) * 144 + (u32)(c & 7) * 16;
                cpasync16(sb_ + off, ah + c * 16);
                cpasync16(sb_ + 18432 + off, al + c * 16);
            }
            cpasync_commit();
        }
    }
    if (tid < 128)
        sB[tid] = (mode == 0) ? ((tid < 64) ? bias[tid] : 0.f) : g_c128[tid];

    int lane = tid & 31;
    int wid  = tid >> 5;
    int wm   = wid & 3;      // rows wm*32..+32
    int wn   = wid >> 2;     // cols wn*64..+64

    u32 aoff = ((wm * 32 + (lane & 15)) * 72 + (lane >> 4) * 8) * 2;
    int brow = wn * 64 + (lane & 7) + (lane >> 4) * 8;
    u32 bHi = sbase + (brow * 72 + ((lane >> 3) & 1) * 8) * 2;
    u32 bLo = bHi + 18432;
    int r = lane >> 2, q = lane & 3;

#pragma unroll 1
    for (int i = 0; i < ntiles; i++) {
        int tile = blockIdx.x + i * PGRID;
        u32 stg = sbase + 36864 + (u32)(i & 1) * 36864;
        u32 aHi = stg + aoff;
        u32 aLo = aHi + 18432;

        if (i < ntiles - 1) cpasync_wait1(); else cpasync_wait0();
        __syncthreads();

        float d[2][8][4];
#pragma unroll
        for (int mt = 0; mt < 2; mt++)
#pragma unroll
            for (int nf = 0; nf < 8; nf++)
#pragma unroll
                for (int j = 0; j < 4; j++) d[mt][nf][j] = 0.f;

        // passes: Ahi*Bhi + Alo*Bhi, then Ahi*Blo
#pragma unroll
        for (int kk = 0; kk < 4; kk++) {
            int ko = kk * 32;
            u32 ah[2][4], al[2][4], bb[4][4];
            ldsm4(ah[0], aHi + ko);
            ldsm4(ah[1], aHi + 2304 + ko);
            ldsm4(al[0], aLo + ko);
            ldsm4(al[1], aLo + 2304 + ko);
#pragma unroll
            for (int p = 0; p < 4; p++) ldsm4(bb[p], bHi + p * 2304 + ko);
#pragma unroll
            for (int mt = 0; mt < 2; mt++)
#pragma unroll
                for (int nf = 0; nf < 8; nf++) {
                    mma16816(d[mt][nf], ah[mt], &bb[nf >> 1][(nf & 1) * 2]);
                    mma16816(d[mt][nf], al[mt], &bb[nf >> 1][(nf & 1) * 2]);
                }
#pragma unroll
            for (int p = 0; p < 4; p++) ldsm4(bb[p], bLo + p * 2304 + ko);
#pragma unroll
            for (int mt = 0; mt < 2; mt++)
#pragma unroll
                for (int nf = 0; nf < 8; nf++)
                    mma16816(d[mt][nf], ah[mt], &bb[nf >> 1][(nf & 1) * 2]);
        }
        __syncthreads();   // all warps done reading this stage

        // prefetch tile i+2 into this stage (overlaps epilogue stores)
        if (i + 2 < ntiles) {
            int t2 = blockIdx.x + (i + 2) * PGRID;
            const char* ah2 = (const char*)(g_hhi + (size_t)t2 * TILE_M * 64);
            const char* al2 = (const char*)(g_hlo + (size_t)t2 * TILE_M * 64);
#pragma unroll
            for (int c = tid; c < 1024; c += 256) {
                u32 off = (u32)(c >> 3) * 144 + (u32)(c & 7) * 16;
                cpasync16(stg + off, ah2 + c * 16);
                cpasync16(stg + 18432 + off, al2 + c * 16);
            }
            cpasync_commit();
        }

        // epilogue
        int nb = tile * TILE_M;
#pragma unroll
        for (int mt = 0; mt < 2; mt++) {
            int row0 = nb + wm * 32 + mt * 16 + r;
#pragma unroll
            for (int nf = 0; nf < 8; nf++) {
                int gcol = wn * 64 + nf * 8 + 2 * q;
                float bx = sB[gcol], by = sB[gcol + 1];
                float2 v0 = make_float2(d[mt][nf][0] + bx, d[mt][nf][1] + by);
                float2 v1 = make_float2(d[mt][nf][2] + bx, d[mt][nf][3] + by);
                if (mode == 1) {
                    v0.x = fmaxf(v0.x, 0.f); v0.y = fmaxf(v0.y, 0.f);
                    v1.x = fmaxf(v1.x, 0.f); v1.y = fmaxf(v1.y, 0.f);
                }
                if (row0 < NN)     *(float2*)(g_pq + row0 * 128 + gcol)       = v0;
                if (row0 + 8 < NN) *(float2*)(g_pq + (row0 + 8) * 128 + gcol) = v1;
            }
        }
    }
}

// ---------------- c128 = ba + g @ Wa[64:128] --------------------------------
__global__ void c128_kernel(const float* __restrict__ Wa,
                            const float* __restrict__ ba) {
    int t = threadIdx.x;  // 128 threads
    float s = ba[t];
#pragma unroll 8
    for (int c = 0; c < 64; c++)
        s += __uint_as_float(g_gmax[c]) * Wa[(64 + c) * 128 + t];
    g_c128[t] = s;
}

// ---------------- head stage 2: out = x + r @ Wb + bb ----------------------
// ONE NODE PER WARP -> grid must cover NN warps = (NN*32)/256 blocks.
__global__ void head2_kernel(const float* __restrict__ Wb,
                             const float* __restrict__ bb,
                             const float* __restrict__ x,
                             float* __restrict__ out) {
    __shared__ float sWb[384];
    for (int i = threadIdx.x; i < 384; i += 256) sWb[i] = Wb[i];
    __syncthreads();
    int w    = (blockIdx.x * blockDim.x + threadIdx.x) >> 5;
    int lane = threadIdx.x & 31;
    if (w >= NN) return;
    float4 r4 = ((const float4*)(g_pq + w * 128))[lane];
    int t = lane * 4;
    float a0 = r4.x * sWb[t * 3 + 0] + r4.y * sWb[t * 3 + 3] +
               r4.z * sWb[t * 3 + 6] + r4.w * sWb[t * 3 + 9];
    float a1 = r4.x * sWb[t * 3 + 1] + r4.y * sWb[t * 3 + 4] +
               r4.z * sWb[t * 3 + 7] + r4.w * sWb[t * 3 + 10];
    float a2 = r4.x * sWb[t * 3 + 2] + r4.y * sWb[t * 3 + 5] +
               r4.z * sWb[t * 3 + 8] + r4.w * sWb[t * 3 + 11];
#pragma unroll
    for (int off = 16; off > 0; off >>= 1) {
        a0 += __shfl_down_sync(0xffffffffu, a0, off);
        a1 += __shfl_down_sync(0xffffffffu, a1, off);
        a2 += __shfl_down_sync(0xffffffffu, a2, off);
    }
    if (lane == 0) {
        out[w * 3 + 0] = x[w * 3 + 0] + bb[0] + a0;
        out[w * 3 + 1] = x[w * 3 + 1] + bb[1] + a1;
        out[w * 3 + 2] = x[w * 3 + 2] + bb[2] + a2;
    }
}

// ---------------- launch ----------------------------------------------------
extern "C" void kernel_launch(void* const* d_in, const int* in_sizes, int n_in,
                              void* d_out, int out_size) {
    (void)in_sizes; (void)n_in; (void)out_size;
    const float* x  = (const float*)d_in[0];
    const int*   ei = (const int*)d_in[1];
    const float* W1 = (const float*)d_in[2];
    const float* b1 = (const float*)d_in[3];
    const float* Wl[4] = {(const float*)d_in[4], (const float*)d_in[6],
                          (const float*)d_in[8], (const float*)d_in[10]};
    const float* bl[4] = {(const float*)d_in[5], (const float*)d_in[7],
                          (const float*)d_in[9], (const float*)d_in[11]};
    const float* Wa = (const float*)d_in[12];
    const float* ba = (const float*)d_in[13];
    const float* Wb = (const float*)d_in[14];
    const float* bb = (const float*)d_in[15];
    float* out = (float*)d_out;

    const int GEMM_SMEM = 111104;
    static bool attr_set = false;
    if (!attr_set) {
        cudaFuncSetAttribute(tc_gemm_kernel,
                             cudaFuncAttributeMaxDynamicSharedMemorySize,
                             GEMM_SMEM);
        attr_set = true;
    }

    convert_kernel<<<(EE + 255) / 256, 256>>>(ei);                        // #1
    layer1_kernel<<<12505, 256>>>(x, W1, b1, Wl[0], Wl[1], Wl[2], Wl[3], Wa); // #2
    edge_kernel<<<(NN * 16) / 256, 256>>>(0);                             // #3

    for (int l = 0; l < 4; l++) {
        tc_gemm_kernel<<<PGRID, 256, GEMM_SMEM>>>(l, bl[l], 0);           // #4 (l=0)
        edge_kernel<<<(NN * 16) / 256, 256>>>(l == 3 ? 1 : 0);
    }

    c128_kernel<<<1, 128>>>(Wa, ba);
    tc_gemm_kernel<<<PGRID, 256, GEMM_SMEM>>>(4, ba, 1);
    head2_kernel<<<(NN * 32) / 256, 256>>>(Wb, bb, x, out);   // 1 node/warp
}